// round 15
// baseline (speedup 1.0000x reference)
#include <cuda_runtime.h>
#include <cuda_fp16.h>
#include <cstdint>

#define NPTS    131072
#define MTILE   64
#define NBLK    (NPTS / MTILE)
#define THREADS 256
#define NCHUNKS 64          // 8 gemms x 8 k-chunks, one global cp.async ring

// ---- smem layout (byte offsets) ----
#define X_OFF    0          // 64x256 fp16, swizzled rows of 512B (32KB)
#define B_OFF    32768      // 3 bufs x [n(256)][k(32)] fp16 = 3x16KB
#define SHG_OFF  81920      // grid feats [m][32] fp32 (8KB)
#define SHA_OFF  90112      // ffn_A scaled [n][8] fp32 (8KB)
#define SHB_OFF  98304      // biases: [0..255]=bs_l, [256..511]=bh_l (2KB)
#define POS_OFF  100352     // 64x3 fp32 (768B)
#define SMEM_BYTES 101120

// weight scratch: [lm(8)][n(256)][k(256)] fp16 = 1MB
__device__ __half g_B[524288];

// ---------- helpers ----------
__device__ __forceinline__ uint32_t smem_u32(const void* p) {
    uint32_t a;
    asm("{ .reg .u64 t; cvta.to.shared.u64 t, %1; cvt.u32.u64 %0, t; }" : "=r"(a) : "l"(p));
    return a;
}
__device__ __forceinline__ void ldsm4(uint32_t* r, uint32_t addr) {
    asm volatile("ldmatrix.sync.aligned.m8n8.x4.shared.b16 {%0,%1,%2,%3}, [%4];"
        : "=r"(r[0]), "=r"(r[1]), "=r"(r[2]), "=r"(r[3]) : "r"(addr));
}
__device__ __forceinline__ void mma16816(float* c, const uint32_t* a, const uint32_t* b) {
    asm volatile("mma.sync.aligned.m16n8k16.row.col.f32.f16.f16.f32 "
        "{%0,%1,%2,%3}, {%4,%5,%6,%7}, {%8,%9}, {%0,%1,%2,%3};"
        : "+f"(c[0]), "+f"(c[1]), "+f"(c[2]), "+f"(c[3])
        : "r"(a[0]), "r"(a[1]), "r"(a[2]), "r"(a[3]), "r"(b[0]), "r"(b[1]));
}

// fast sin: 2-term Cody-Waite + MUFU (validated: rel_err contribution ~1e-6)
__device__ __forceinline__ float fast_sin(float x) {
    float k = rintf(x * 0.15915494309189535f);
    float r = fmaf(k, -6.2831854820251465f, x);
    r = fmaf(k, 1.7484556e-7f, r);
    return __sinf(r);
}

// X smem: row m = 512B (256 fp16), 16B chunk c swizzled c^(m&7)
__device__ __forceinline__ void store_x(char* sm, int m, int k, float x) {
    uint32_t c = (uint32_t)(k >> 3);
    uint32_t o = ((uint32_t)m << 9) + ((c ^ (uint32_t)(m & 7)) << 4) + (((uint32_t)k & 7u) << 1);
    *(__half*)(sm + X_OFF + o) = __float2half_rn(x);
}

// ---------- prep: fp16-round + transpose weights to g_B[lm][n][k] ----------
__global__ void prep_kernel(const float* __restrict__ Ws, const float* __restrict__ Wh) {
    int i = blockIdx.x * blockDim.x + threadIdx.x;
    if (i >= 8 * 65536) return;
    int lm = i >> 16;               // l*2 + mat
    int e  = i & 65535;             // k*256 + n
    int k = e >> 8, n = e & 255;
    const float* W = (lm & 1) ? Wh : Ws;
    g_B[(lm << 16) + (n << 8) + k] = __float2half_rn(W[(lm >> 1) * 65536 + e]);
}

// ---------- ring prefetch: global chunk g -> buffer g%3, one commit group ----------
// B chunk: [256n][32k] fp16 (16KB), 64B rows, swz cin^((n>>1)&3)
__device__ __forceinline__ void prefetch_chunk(uint32_t sb, int g, int t) {
    const int lm = g >> 3, kc = g & 7, buf = g % 3;
#pragma unroll
    for (int ii = 0; ii < 4; ii++) {
        int i = t + ii * THREADS;                 // 0..1023 16B units
        int n = i >> 2, cin = i & 3;
        const __half* gp = g_B + (lm << 16) + (n << 8) + (kc << 5) + (cin << 3);
        uint32_t dst = sb + B_OFF + (uint32_t)buf * 16384u
                     + ((uint32_t)n << 6) + ((uint32_t)(cin ^ ((n >> 1) & 3)) << 4);
        asm volatile("cp.async.cg.shared.global [%0], [%1], 16;" :: "r"(dst), "l"(gp));
    }
    asm volatile("cp.async.commit_group;" ::: "memory");
}

// ---------- fp16 GEMM: acc(32m x 64n per warp) = X @ W over K=256 (8 ring chunks) ----------
__device__ __forceinline__ void run_gemm(uint32_t sb, int gbase, int t, int lane,
                                         int wm, int wn, float acc[2][8][4])
{
#pragma unroll
    for (int mt = 0; mt < 2; mt++)
#pragma unroll
        for (int nt = 0; nt < 8; nt++)
#pragma unroll
            for (int r = 0; r < 4; r++) acc[mt][nt][r] = 0.0f;

    const int arow = lane & 15;
    const int asel = lane >> 4;
    const int quad = lane >> 3, r8 = lane & 7;
    const int brow_off = ((quad >> 1) << 3) + r8;
    const int bsel = quad & 1;

    for (int kc = 0; kc < 8; kc++) {
        const int g = gbase + kc;
        // steady state: one chunk in flight beyond g -> wait_group 1; tail -> 0
        if (g == NCHUNKS - 1)
            asm volatile("cp.async.wait_group 0;" ::: "memory");
        else
            asm volatile("cp.async.wait_group 1;" ::: "memory");
        __syncthreads();                          // chunk g ready; buf (g+2)%3 drained
        if (g + 2 < NCHUNKS)
            prefetch_chunk(sb, g + 2, t);
        const uint32_t bbase = sb + B_OFF + (uint32_t)(g % 3) * 16384u;
#pragma unroll
        for (int ks = 0; ks < 2; ks++) {
            uint32_t ah[2][4];
            const int cidx = (kc << 2) + (ks << 1) + asel;   // global 16B k-chunk
#pragma unroll
            for (int mt = 0; mt < 2; mt++) {
                int row = wm * 32 + mt * 16 + arow;
                uint32_t off = ((uint32_t)row << 9) + ((uint32_t)(cidx ^ (row & 7)) << 4);
                ldsm4(ah[mt], sb + X_OFF + off);
            }
#pragma unroll
            for (int nt = 0; nt < 4; nt++) {
                uint32_t bh[4];
                int nrow = wn * 64 + nt * 16 + brow_off;
                int cin = (ks << 1) + bsel;
                uint32_t boff = ((uint32_t)nrow << 6)
                              + ((uint32_t)(cin ^ ((nrow >> 1) & 3)) << 4);
                ldsm4(bh, bbase + boff);
#pragma unroll
                for (int mt = 0; mt < 2; mt++) {
                    mma16816(acc[mt][nt * 2],     ah[mt], bh);
                    mma16816(acc[mt][nt * 2 + 1], ah[mt], bh + 2);
                }
            }
        }
    }
    __syncthreads();                              // all X/B reads done before epilogue writes
}

// ---------- main ----------
__global__ void __launch_bounds__(THREADS, 2)
ffb_main(const float* __restrict__ in_pos, const float* __restrict__ table,
         const float* __restrict__ ffn_A, const float* __restrict__ W0,
         const float* __restrict__ b0,    const float* __restrict__ bs,
         const float* __restrict__ bh,    float* __restrict__ out)
{
    extern __shared__ char sm[];
    const uint32_t sb = smem_u32(sm);
    const int t = threadIdx.x, w = t >> 5, lane = t & 31;
    const int wm = w & 1, wn = w >> 1;             // 2m x 4n warp grid
    const int base = blockIdx.x * MTILE;

    float* shpos = (float*)(sm + POS_OFF);
    float* shg   = (float*)(sm + SHG_OFF);
    float* shA   = (float*)(sm + SHA_OFF);
    float* shb   = (float*)(sm + SHB_OFF);

    // warm the ring: chunks 0,1 load during encode + layer 0
    prefetch_chunk(sb, 0, t);
    prefetch_chunk(sb, 1, t);

    if (t < 3 * MTILE) shpos[t] = in_pos[base * 3 + t];
    __syncthreads();

    // ---- hash-grid encode: 512 tasks = 64 pts x 8 corners (bit-exact, validated) ----
#pragma unroll
    for (int rep = 0; rep < 2; rep++) {
        int task = t + THREADS * rep;
        int m = task >> 3, c = task & 7;
        const unsigned ox = (c >> 2) & 1u, oy = (c >> 1) & 1u, oz = c & 1u;
        const float px = (shpos[3*m + 0] + 1.0f) * 0.5f;
        const float py = (shpos[3*m + 1] + 1.0f) * 0.5f;
        const float pz = (shpos[3*m + 2] + 1.0f) * 0.5f;
#pragma unroll
        for (int l = 0; l < 4; l++) {
            const float res = (float)(16 << l);
            float sx = px*res, sy = py*res, sz = pz*res;
            float fx = floorf(sx), fy = floorf(sy), fz = floorf(sz);
            float rx = sx-fx, ry = sy-fy, rz = sz-fz;
            unsigned ux = (unsigned)fx + ox, uy = (unsigned)fy + oy, uz = (unsigned)fz + oz;
            unsigned idx = (ux ^ (uy * 2654435761u) ^ (uz * 805459861u)) & 32767u;
            const float4* fp = (const float4*)(table + ((size_t)(l << 15) + idx) * 8);
            float4 f0 = __ldg(fp), f1 = __ldg(fp + 1);
            float wt = (ox ? rx : 1.0f-rx) * (oy ? ry : 1.0f-ry) * (oz ? rz : 1.0f-rz);
            float v[8] = { f0.x*wt, f0.y*wt, f0.z*wt, f0.w*wt,
                           f1.x*wt, f1.y*wt, f1.z*wt, f1.w*wt };
#pragma unroll
            for (int s = 1; s < 8; s <<= 1)
#pragma unroll
                for (int j = 0; j < 8; j++)
                    v[j] += __shfl_xor_sync(0xffffffffu, v[j], s);
            if (c == 0) {
                float* gp = shg + m * 32 + l * 8;
#pragma unroll
                for (int j = 0; j < 8; j++) gp[j] = v[j];
            }
        }
    }

    // ---- layer 0: X = sin(pos @ W0 + b0) -> fp16 smem ----
    {
        const int k = t;
        const float wx = __ldg(W0 + k), wy = __ldg(W0 + 256 + k),
                    wz = __ldg(W0 + 512 + k), bb = __ldg(b0 + k);
#pragma unroll 8
        for (int m = 0; m < MTILE; m++) {
            float a = fmaf(shpos[3*m], wx, fmaf(shpos[3*m+1], wy, fmaf(shpos[3*m+2], wz, bb)));
            store_x(sm, m, k, fast_sin(a));
        }
    }

    float acc[2][8][4];

#pragma unroll 1
    for (int l = 0; l < 4; l++) {
        __syncthreads();   // guard shA/shb overwrite vs prev layer's epilogue reads
        const float gsc = 6.2831853071795864f * (float)(1 << l);
#pragma unroll
        for (int i = t; i < 2048; i += THREADS) {
            int n = i >> 3, f = i & 7;
            shA[i] = __ldg(ffn_A + ((l * 8 + f) << 8) + n) * gsc;
        }
        shb[t]       = __ldg(bs + (l << 8) + t);
        shb[256 + t] = __ldg(bh + (l << 8) + t);
        // ordered before epilogue reads by run_gemm's internal __syncthreads

        // GEMM1: S = X @ Ws[l]  (ring chunks [l*16, l*16+8))
        run_gemm(sb, l * 16, t, lane, wm, wn, acc);

        // epilogue1: x = sin(S+bs) + sin(grid.A'); write new X (fp16)
#pragma unroll
        for (int mt = 0; mt < 2; mt++) {
#pragma unroll
            for (int h = 0; h < 2; h++) {
                const int m = wm * 32 + mt * 16 + (lane >> 2) + h * 8;
                const float* gp = shg + m * 32 + l * 8;
                float4 g0 = *(const float4*)gp, g1 = *(const float4*)(gp + 4);
#pragma unroll
                for (int nt = 0; nt < 8; nt++) {
                    const int n = wn * 64 + nt * 8 + (lane & 3) * 2;
#pragma unroll
                    for (int u = 0; u < 2; u++) {
                        float S = acc[mt][nt][h * 2 + u] + shb[n + u];
                        const float4 a0 = *(const float4*)(shA + (n + u) * 8);
                        const float4 a1 = *(const float4*)(shA + (n + u) * 8 + 4);
                        float g = g0.x * a0.x;
                        g = fmaf(g0.y, a0.y, g); g = fmaf(g0.z, a0.z, g);
                        g = fmaf(g0.w, a0.w, g); g = fmaf(g1.x, a1.x, g);
                        g = fmaf(g1.y, a1.y, g); g = fmaf(g1.z, a1.z, g);
                        g = fmaf(g1.w, a1.w, g);
                        store_x(sm, m, n + u, fast_sin(S) + fast_sin(g));
                    }
                }
            }
        }
        // GEMM2 reads of X ordered after these writes by its first __syncthreads

        // GEMM2: D = X @ Wh[l]  (ring chunks [l*16+8, l*16+16))
        run_gemm(sb, l * 16 + 8, t, lane, wm, wn, acc);

        // epilogue2: out[m][n] (+)= sin(D + bh)   (exclusive cell ownership)
#pragma unroll
        for (int mt = 0; mt < 2; mt++) {
#pragma unroll
            for (int h = 0; h < 2; h++) {
                const int m = wm * 32 + mt * 16 + (lane >> 2) + h * 8;
                float* op = out + (size_t)(base + m) * 256;
#pragma unroll
                for (int nt = 0; nt < 8; nt++) {
                    const int n = wn * 64 + nt * 8 + (lane & 3) * 2;
                    float v0 = fast_sin(acc[mt][nt][h * 2 + 0] + shb[256 + n]);
                    float v1 = fast_sin(acc[mt][nt][h * 2 + 1] + shb[256 + n + 1]);
                    float2* p = (float2*)(op + n);
                    if (l == 0) {
                        *p = make_float2(v0, v1);
                    } else {
                        float2 o = *p;
                        *p = make_float2(o.x + v0, o.y + v1);
                    }
                }
            }
        }
    }
}

extern "C" void kernel_launch(void* const* d_in, const int* in_sizes, int n_in,
                              void* d_out, int out_size)
{
    const float* in_pos = (const float*)d_in[0];
    const float* table  = (const float*)d_in[1];
    const float* ffn_A  = (const float*)d_in[2];
    const float* W0     = (const float*)d_in[3];
    const float* b0     = (const float*)d_in[4];
    const float* Ws     = (const float*)d_in[5];
    const float* bs     = (const float*)d_in[6];
    const float* Wh     = (const float*)d_in[7];
    const float* bh     = (const float*)d_in[8];
    float* out = (float*)d_out;

    cudaFuncSetAttribute(ffb_main, cudaFuncAttributeMaxDynamicSharedMemorySize, SMEM_BYTES);

    prep_kernel<<<(8 * 65536 + 255) / 256, 256>>>(Ws, Wh);
    ffb_main<<<NBLK, THREADS, SMEM_BYTES>>>(in_pos, table, ffn_A, W0, b0, bs, bh, out);
}

// round 16
// speedup vs baseline: 1.2506x; 1.2506x over previous
#include <cuda_runtime.h>
#include <cuda_fp16.h>
#include <cstdint>

#define NPTS    131072
#define MTILE   64
#define NBLK    (NPTS / MTILE)
#define THREADS 256

// ---- smem layout (byte offsets) ----
#define X_OFF    0          // 64x256 fp16, swizzled rows of 512B (32KB)
#define B_OFF    32768      // 2 bufs x [n(256)][k(32)] fp16 = 2x16KB
#define SHG_OFF  65536      // grid feats [m][32] fp32 (8KB)
#define SHA_OFF  73728      // ffn_A scaled [n][8] fp32 (8KB)
#define SHB_OFF  81920      // biases: [0..255]=bs_l, [256..511]=bh_l (2KB)
#define POS_OFF  83968      // 64x3 fp32 (768B)
#define SMEM_BYTES 84736

// weight scratch: [lm(8)][n(256)][k(256)] fp16 = 1MB
__device__ __half g_B[524288];

// ---------- helpers ----------
__device__ __forceinline__ uint32_t smem_u32(const void* p) {
    uint32_t a;
    asm("{ .reg .u64 t; cvta.to.shared.u64 t, %1; cvt.u32.u64 %0, t; }" : "=r"(a) : "l"(p));
    return a;
}
__device__ __forceinline__ void ldsm4(uint32_t* r, uint32_t addr) {
    asm volatile("ldmatrix.sync.aligned.m8n8.x4.shared.b16 {%0,%1,%2,%3}, [%4];"
        : "=r"(r[0]), "=r"(r[1]), "=r"(r[2]), "=r"(r[3]) : "r"(addr));
}
__device__ __forceinline__ void mma16816(float* c, const uint32_t* a, const uint32_t* b) {
    asm volatile("mma.sync.aligned.m16n8k16.row.col.f32.f16.f16.f32 "
        "{%0,%1,%2,%3}, {%4,%5,%6,%7}, {%8,%9}, {%0,%1,%2,%3};"
        : "+f"(c[0]), "+f"(c[1]), "+f"(c[2]), "+f"(c[3])
        : "r"(a[0]), "r"(a[1]), "r"(a[2]), "r"(a[3]), "r"(b[0]), "r"(b[1]));
}

// fast sin: 2-term Cody-Waite + MUFU (validated: rel_err contribution ~1e-6)
__device__ __forceinline__ float fast_sin(float x) {
    float k = rintf(x * 0.15915494309189535f);
    float r = fmaf(k, -6.2831854820251465f, x);
    r = fmaf(k, 1.7484556e-7f, r);
    return __sinf(r);
}

// X smem: row m = 512B (256 fp16), 16B chunk c swizzled c^(m&7)
__device__ __forceinline__ void store_x(char* sm, int m, int k, float x) {
    uint32_t c = (uint32_t)(k >> 3);
    uint32_t o = ((uint32_t)m << 9) + ((c ^ (uint32_t)(m & 7)) << 4) + (((uint32_t)k & 7u) << 1);
    *(__half*)(sm + X_OFF + o) = __float2half_rn(x);
}

// ---------- prep: fp16-round + transpose weights to g_B[lm][n][k] ----------
__global__ void prep_kernel(const float* __restrict__ Ws, const float* __restrict__ Wh) {
    int i = blockIdx.x * blockDim.x + threadIdx.x;
    if (i >= 8 * 65536) return;
    int lm = i >> 16;               // l*2 + mat
    int e  = i & 65535;             // k*256 + n
    int k = e >> 8, n = e & 255;
    const float* W = (lm & 1) ? Wh : Ws;
    g_B[(lm << 16) + (n << 8) + k] = __float2half_rn(W[(lm >> 1) * 65536 + e]);
}

// ---------- B chunk loader: [256n][32k] fp16 (16KB), 64B rows, swz cin^((n>>1)&3) ----------
__device__ __forceinline__ void load_b_chunk(uint32_t sb, int lm, int kc, int buf, int t) {
#pragma unroll
    for (int ii = 0; ii < 4; ii++) {
        int i = t + ii * THREADS;                 // 0..1023 16B units
        int n = i >> 2, cin = i & 3;
        const __half* g = g_B + (lm << 16) + (n << 8) + (kc << 5) + (cin << 3);
        uint32_t dst = sb + B_OFF + ((uint32_t)buf << 14)
                     + ((uint32_t)n << 6) + ((uint32_t)(cin ^ ((n >> 1) & 3)) << 4);
        asm volatile("cp.async.cg.shared.global [%0], [%1], 16;" :: "r"(dst), "l"(g));
    }
}

// ---------- fp16 GEMM: acc(32m x 64n per warp) = X @ W, K=256 in 8 chunks ----------
__device__ __forceinline__ void run_gemm(uint32_t sb, int lm, int t, int lane,
                                         int wm, int wn, float acc[2][8][4])
{
#pragma unroll
    for (int mt = 0; mt < 2; mt++)
#pragma unroll
        for (int nt = 0; nt < 8; nt++)
#pragma unroll
            for (int r = 0; r < 4; r++) acc[mt][nt][r] = 0.0f;

    const int arow = lane & 15;
    const int asel = lane >> 4;
    const int quad = lane >> 3, r8 = lane & 7;
    const int brow_off = ((quad >> 1) << 3) + r8;
    const int bsel = quad & 1;

    load_b_chunk(sb, lm, 0, 0, t);
    asm volatile("cp.async.commit_group;" ::: "memory");

    for (int kc = 0; kc < 8; kc++) {
        asm volatile("cp.async.wait_group 0;" ::: "memory");
        __syncthreads();                          // chunk ready; prev reads done
        if (kc < 7) {
            load_b_chunk(sb, lm, kc + 1, (kc + 1) & 1, t);
            asm volatile("cp.async.commit_group;" ::: "memory");
        }
        const uint32_t bbase = sb + B_OFF + ((uint32_t)(kc & 1) << 14);
#pragma unroll
        for (int ks = 0; ks < 2; ks++) {
            uint32_t ah[2][4];
            const int cidx = (kc << 2) + (ks << 1) + asel;   // global 16B k-chunk
#pragma unroll
            for (int mt = 0; mt < 2; mt++) {
                int row = wm * 32 + mt * 16 + arow;
                uint32_t off = ((uint32_t)row << 9) + ((uint32_t)(cidx ^ (row & 7)) << 4);
                ldsm4(ah[mt], sb + X_OFF + off);
            }
#pragma unroll
            for (int nt = 0; nt < 4; nt++) {
                uint32_t bh[4];
                int nrow = wn * 64 + nt * 16 + brow_off;
                int cin = (ks << 1) + bsel;
                uint32_t boff = ((uint32_t)nrow << 6)
                              + ((uint32_t)(cin ^ ((nrow >> 1) & 3)) << 4);
                ldsm4(bh, bbase + boff);
#pragma unroll
                for (int mt = 0; mt < 2; mt++) {
                    mma16816(acc[mt][nt * 2],     ah[mt], bh);
                    mma16816(acc[mt][nt * 2 + 1], ah[mt], bh + 2);
                }
            }
        }
    }
    __syncthreads();                              // all X/B reads done before epilogue writes
}

// ---------- main ----------
__global__ void __launch_bounds__(THREADS, 2)
ffb_main(const float* __restrict__ in_pos, const float* __restrict__ table,
         const float* __restrict__ ffn_A, const float* __restrict__ W0,
         const float* __restrict__ b0,    const float* __restrict__ bs,
         const float* __restrict__ bh,    float* __restrict__ out)
{
    extern __shared__ char sm[];
    const uint32_t sb = smem_u32(sm);
    const int t = threadIdx.x, w = t >> 5, lane = t & 31;
    const int wm = w & 1, wn = w >> 1;             // 2m x 4n warp grid
    const int base = blockIdx.x * MTILE;

    float* shpos = (float*)(sm + POS_OFF);
    float* shg   = (float*)(sm + SHG_OFF);
    float* shA   = (float*)(sm + SHA_OFF);
    float* shb   = (float*)(sm + SHB_OFF);

    if (t < 3 * MTILE) shpos[t] = in_pos[base * 3 + t];
    __syncthreads();

    // ---- hash-grid encode: 512 tasks = 64 pts x 8 corners (bit-exact, validated) ----
#pragma unroll
    for (int rep = 0; rep < 2; rep++) {
        int task = t + THREADS * rep;
        int m = task >> 3, c = task & 7;
        const unsigned ox = (c >> 2) & 1u, oy = (c >> 1) & 1u, oz = c & 1u;
        const float px = (shpos[3*m + 0] + 1.0f) * 0.5f;
        const float py = (shpos[3*m + 1] + 1.0f) * 0.5f;
        const float pz = (shpos[3*m + 2] + 1.0f) * 0.5f;
#pragma unroll
        for (int l = 0; l < 4; l++) {
            const float res = (float)(16 << l);
            float sx = px*res, sy = py*res, sz = pz*res;
            float fx = floorf(sx), fy = floorf(sy), fz = floorf(sz);
            float rx = sx-fx, ry = sy-fy, rz = sz-fz;
            unsigned ux = (unsigned)fx + ox, uy = (unsigned)fy + oy, uz = (unsigned)fz + oz;
            unsigned idx = (ux ^ (uy * 2654435761u) ^ (uz * 805459861u)) & 32767u;
            const float4* fp = (const float4*)(table + ((size_t)(l << 15) + idx) * 8);
            float4 f0 = __ldg(fp), f1 = __ldg(fp + 1);
            float wt = (ox ? rx : 1.0f-rx) * (oy ? ry : 1.0f-ry) * (oz ? rz : 1.0f-rz);
            float v[8] = { f0.x*wt, f0.y*wt, f0.z*wt, f0.w*wt,
                           f1.x*wt, f1.y*wt, f1.z*wt, f1.w*wt };
#pragma unroll
            for (int s = 1; s < 8; s <<= 1)
#pragma unroll
                for (int j = 0; j < 8; j++)
                    v[j] += __shfl_xor_sync(0xffffffffu, v[j], s);
            if (c == 0) {
                float* gp = shg + m * 32 + l * 8;
#pragma unroll
                for (int j = 0; j < 8; j++) gp[j] = v[j];
            }
        }
    }

    // ---- layer 0: X = sin(pos @ W0 + b0) -> fp16 smem ----
    {
        const int k = t;
        const float wx = __ldg(W0 + k), wy = __ldg(W0 + 256 + k),
                    wz = __ldg(W0 + 512 + k), bb = __ldg(b0 + k);
#pragma unroll 8
        for (int m = 0; m < MTILE; m++) {
            float a = fmaf(shpos[3*m], wx, fmaf(shpos[3*m+1], wy, fmaf(shpos[3*m+2], wz, bb)));
            store_x(sm, m, k, fast_sin(a));
        }
    }

    float acc[2][8][4];

#pragma unroll 1
    for (int l = 0; l < 4; l++) {
        __syncthreads();   // guard shA/shb overwrite vs prev layer's epilogue reads
        const float gsc = 6.2831853071795864f * (float)(1 << l);
#pragma unroll
        for (int i = t; i < 2048; i += THREADS) {
            int n = i >> 3, f = i & 7;
            shA[i] = __ldg(ffn_A + ((l * 8 + f) << 8) + n) * gsc;
        }
        shb[t]       = __ldg(bs + (l << 8) + t);
        shb[256 + t] = __ldg(bh + (l << 8) + t);
        // ordered before epilogue reads by run_gemm's internal __syncthreads

        // GEMM1: S = X @ Ws[l]
        run_gemm(sb, l * 2, t, lane, wm, wn, acc);

        // epilogue1: x = sin(S+bs) + sin(grid.A'); write new X (fp16)
        // hoisted: grid rows (4 x 8 regs) once; shA cols once per nt; half2 stores
        {
            float gre[4][8];
#pragma unroll
            for (int mh = 0; mh < 4; mh++) {
                const int m = wm * 32 + (mh >> 1) * 16 + (lane >> 2) + (mh & 1) * 8;
                const float4 G0 = *(const float4*)(shg + m * 32 + l * 8);
                const float4 G1 = *(const float4*)(shg + m * 32 + l * 8 + 4);
                gre[mh][0] = G0.x; gre[mh][1] = G0.y; gre[mh][2] = G0.z; gre[mh][3] = G0.w;
                gre[mh][4] = G1.x; gre[mh][5] = G1.y; gre[mh][6] = G1.z; gre[mh][7] = G1.w;
            }
#pragma unroll
            for (int nt = 0; nt < 8; nt++) {
                const int n0 = wn * 64 + nt * 8 + (lane & 3) * 2;
                const float4 a00 = *(const float4*)(shA + n0 * 8);
                const float4 a01 = *(const float4*)(shA + n0 * 8 + 4);
                const float4 a10 = *(const float4*)(shA + (n0 + 1) * 8);
                const float4 a11 = *(const float4*)(shA + (n0 + 1) * 8 + 4);
                const float b0v = shb[n0], b1v = shb[n0 + 1];
#pragma unroll
                for (int mh = 0; mh < 4; mh++) {
                    const int mt = mh >> 1, h = mh & 1;
                    const int m = wm * 32 + mt * 16 + (lane >> 2) + h * 8;
                    float S0 = acc[mt][nt][h * 2 + 0] + b0v;
                    float S1 = acc[mt][nt][h * 2 + 1] + b1v;
                    float ga = gre[mh][0] * a00.x;
                    ga = fmaf(gre[mh][1], a00.y, ga); ga = fmaf(gre[mh][2], a00.z, ga);
                    ga = fmaf(gre[mh][3], a00.w, ga); ga = fmaf(gre[mh][4], a01.x, ga);
                    ga = fmaf(gre[mh][5], a01.y, ga); ga = fmaf(gre[mh][6], a01.z, ga);
                    ga = fmaf(gre[mh][7], a01.w, ga);
                    float gb = gre[mh][0] * a10.x;
                    gb = fmaf(gre[mh][1], a10.y, gb); gb = fmaf(gre[mh][2], a10.z, gb);
                    gb = fmaf(gre[mh][3], a10.w, gb); gb = fmaf(gre[mh][4], a11.x, gb);
                    gb = fmaf(gre[mh][5], a11.y, gb); gb = fmaf(gre[mh][6], a11.z, gb);
                    gb = fmaf(gre[mh][7], a11.w, gb);
                    float x0 = fast_sin(S0) + fast_sin(ga);
                    float x1 = fast_sin(S1) + fast_sin(gb);
                    // half2 store: n0 even -> both halves in same 16B chunk, 4B aligned
                    uint32_t c = (uint32_t)(n0 >> 3);
                    uint32_t o = ((uint32_t)m << 9) + ((c ^ (uint32_t)(m & 7)) << 4)
                               + (((uint32_t)n0 & 7u) << 1);
                    *(__half2*)(sm + X_OFF + o) =
                        __halves2half2(__float2half_rn(x0), __float2half_rn(x1));
                }
            }
        }
        // GEMM2 reads of X ordered after these writes by its first __syncthreads

        // GEMM2: D = X @ Wh[l]
        run_gemm(sb, l * 2 + 1, t, lane, wm, wn, acc);

        // epilogue2: out[m][n] (+)= sin(D + bh)   (exclusive cell ownership)
#pragma unroll
        for (int mt = 0; mt < 2; mt++) {
#pragma unroll
            for (int h = 0; h < 2; h++) {
                const int m = wm * 32 + mt * 16 + (lane >> 2) + h * 8;
                float* op = out + (size_t)(base + m) * 256;
#pragma unroll
                for (int nt = 0; nt < 8; nt++) {
                    const int n = wn * 64 + nt * 8 + (lane & 3) * 2;
                    float v0 = fast_sin(acc[mt][nt][h * 2 + 0] + shb[256 + n]);
                    float v1 = fast_sin(acc[mt][nt][h * 2 + 1] + shb[256 + n + 1]);
                    float2* p = (float2*)(op + n);
                    if (l == 0) {
                        *p = make_float2(v0, v1);
                    } else {
                        float2 o = *p;
                        *p = make_float2(o.x + v0, o.y + v1);
                    }
                }
            }
        }
    }
}

extern "C" void kernel_launch(void* const* d_in, const int* in_sizes, int n_in,
                              void* d_out, int out_size)
{
    const float* in_pos = (const float*)d_in[0];
    const float* table  = (const float*)d_in[1];
    const float* ffn_A  = (const float*)d_in[2];
    const float* W0     = (const float*)d_in[3];
    const float* b0     = (const float*)d_in[4];
    const float* Ws     = (const float*)d_in[5];
    const float* bs     = (const float*)d_in[6];
    const float* Wh     = (const float*)d_in[7];
    const float* bh     = (const float*)d_in[8];
    float* out = (float*)d_out;

    cudaFuncSetAttribute(ffb_main, cudaFuncAttributeMaxDynamicSharedMemorySize, SMEM_BYTES);

    prep_kernel<<<(8 * 65536 + 255) / 256, 256>>>(Ws, Wh);
    ffb_main<<<NBLK, THREADS, SMEM_BYTES>>>(in_pos, table, ffn_A, W0, b0, bs, bh, out);
}

// round 17
// speedup vs baseline: 1.4499x; 1.1594x over previous
#include <cuda_runtime.h>
#include <cuda_fp16.h>
#include <cstdint>

#define NPTS    131072
#define MTILE   64
#define NBLK    (NPTS / MTILE)
#define THREADS 256

// ---- smem layout (byte offsets) ----
#define X_OFF    0          // 64x256 fp16, swizzled rows of 512B (32KB)
#define B_OFF    32768      // 2 bufs x [n(256)][k(32)] fp16 = 2x16KB
#define SHGH_OFF 65536      // grid feats fp16 [l(4)][m(64)][f(8)] = 16B rows (4KB)
#define SHAH_OFF 69632      // A' fp16 [n(256)][f(8)] = 16B rows (4KB)
#define SHB_OFF  73728      // biases: [0..255]=bs_l, [256..511]=bh_l fp32 (2KB)
#define POS_OFF  75776      // 64x3 fp32 (768B)
#define SMEM_BYTES 76544

// weight scratch: [lm(8)][n(256)][k(256)] fp16 = 1MB
__device__ __half g_B[524288];

// ---------- helpers ----------
__device__ __forceinline__ uint32_t smem_u32(const void* p) {
    uint32_t a;
    asm("{ .reg .u64 t; cvta.to.shared.u64 t, %1; cvt.u32.u64 %0, t; }" : "=r"(a) : "l"(p));
    return a;
}
__device__ __forceinline__ void ldsm4(uint32_t* r, uint32_t addr) {
    asm volatile("ldmatrix.sync.aligned.m8n8.x4.shared.b16 {%0,%1,%2,%3}, [%4];"
        : "=r"(r[0]), "=r"(r[1]), "=r"(r[2]), "=r"(r[3]) : "r"(addr));
}
__device__ __forceinline__ void ldsm2(uint32_t* r, uint32_t addr) {
    asm volatile("ldmatrix.sync.aligned.m8n8.x2.shared.b16 {%0,%1}, [%2];"
        : "=r"(r[0]), "=r"(r[1]) : "r"(addr));
}
__device__ __forceinline__ void mma16816(float* c, const uint32_t* a, const uint32_t* b) {
    asm volatile("mma.sync.aligned.m16n8k16.row.col.f32.f16.f16.f32 "
        "{%0,%1,%2,%3}, {%4,%5,%6,%7}, {%8,%9}, {%0,%1,%2,%3};"
        : "+f"(c[0]), "+f"(c[1]), "+f"(c[2]), "+f"(c[3])
        : "r"(a[0]), "r"(a[1]), "r"(a[2]), "r"(a[3]), "r"(b[0]), "r"(b[1]));
}
__device__ __forceinline__ void mma16808(float* c, const uint32_t* a, uint32_t b) {
    asm volatile("mma.sync.aligned.m16n8k8.row.col.f32.f16.f16.f32 "
        "{%0,%1,%2,%3}, {%4,%5}, {%6}, {%0,%1,%2,%3};"
        : "+f"(c[0]), "+f"(c[1]), "+f"(c[2]), "+f"(c[3])
        : "r"(a[0]), "r"(a[1]), "r"(b));
}

// X smem: row m = 512B (256 fp16), 16B chunk c swizzled c^(m&7)
__device__ __forceinline__ void store_x(char* sm, int m, int k, float x) {
    uint32_t c = (uint32_t)(k >> 3);
    uint32_t o = ((uint32_t)m << 9) + ((c ^ (uint32_t)(m & 7)) << 4) + (((uint32_t)k & 7u) << 1);
    *(__half*)(sm + X_OFF + o) = __float2half_rn(x);
}

// ---------- prep: fp16-round + transpose weights to g_B[lm][n][k] ----------
__global__ void prep_kernel(const float* __restrict__ Ws, const float* __restrict__ Wh) {
    int i = blockIdx.x * blockDim.x + threadIdx.x;
    if (i >= 8 * 65536) return;
    int lm = i >> 16;               // l*2 + mat
    int e  = i & 65535;             // k*256 + n
    int k = e >> 8, n = e & 255;
    const float* W = (lm & 1) ? Wh : Ws;
    g_B[(lm << 16) + (n << 8) + k] = __float2half_rn(W[(lm >> 1) * 65536 + e]);
}

// ---------- B chunk loader: [256n][32k] fp16 (16KB), 64B rows, swz cin^((n>>1)&3) ----------
__device__ __forceinline__ void load_b_chunk(uint32_t sb, int lm, int kc, int buf, int t) {
#pragma unroll
    for (int ii = 0; ii < 4; ii++) {
        int i = t + ii * THREADS;                 // 0..1023 16B units
        int n = i >> 2, cin = i & 3;
        const __half* g = g_B + (lm << 16) + (n << 8) + (kc << 5) + (cin << 3);
        uint32_t dst = sb + B_OFF + ((uint32_t)buf << 14)
                     + ((uint32_t)n << 6) + ((uint32_t)(cin ^ ((n >> 1) & 3)) << 4);
        asm volatile("cp.async.cg.shared.global [%0], [%1], 16;" :: "r"(dst), "l"(g));
    }
}

// ---------- fp16 GEMM: acc(32m x 64n per warp) = X @ W, K=256 in 8 chunks ----------
__device__ __forceinline__ void run_gemm(uint32_t sb, int lm, int t, int lane,
                                         int wm, int wn, float acc[2][8][4])
{
#pragma unroll
    for (int mt = 0; mt < 2; mt++)
#pragma unroll
        for (int nt = 0; nt < 8; nt++)
#pragma unroll
            for (int r = 0; r < 4; r++) acc[mt][nt][r] = 0.0f;

    const int arow = lane & 15;
    const int asel = lane >> 4;
    const int quad = lane >> 3, r8 = lane & 7;
    const int brow_off = ((quad >> 1) << 3) + r8;
    const int bsel = quad & 1;

    load_b_chunk(sb, lm, 0, 0, t);
    asm volatile("cp.async.commit_group;" ::: "memory");

    for (int kc = 0; kc < 8; kc++) {
        asm volatile("cp.async.wait_group 0;" ::: "memory");
        __syncthreads();                          // chunk ready; prev reads done
        if (kc < 7) {
            load_b_chunk(sb, lm, kc + 1, (kc + 1) & 1, t);
            asm volatile("cp.async.commit_group;" ::: "memory");
        }
        const uint32_t bbase = sb + B_OFF + ((uint32_t)(kc & 1) << 14);
#pragma unroll
        for (int ks = 0; ks < 2; ks++) {
            uint32_t ah[2][4];
            const int cidx = (kc << 2) + (ks << 1) + asel;   // global 16B k-chunk
#pragma unroll
            for (int mt = 0; mt < 2; mt++) {
                int row = wm * 32 + mt * 16 + arow;
                uint32_t off = ((uint32_t)row << 9) + ((uint32_t)(cidx ^ (row & 7)) << 4);
                ldsm4(ah[mt], sb + X_OFF + off);
            }
#pragma unroll
            for (int nt = 0; nt < 4; nt++) {
                uint32_t bh[4];
                int nrow = wn * 64 + nt * 16 + brow_off;
                int cin = (ks << 1) + bsel;
                uint32_t boff = ((uint32_t)nrow << 6)
                              + ((uint32_t)(cin ^ ((nrow >> 1) & 3)) << 4);
                ldsm4(bh, bbase + boff);
#pragma unroll
                for (int mt = 0; mt < 2; mt++) {
                    mma16816(acc[mt][nt * 2],     ah[mt], bh);
                    mma16816(acc[mt][nt * 2 + 1], ah[mt], bh + 2);
                }
            }
        }
    }
    __syncthreads();                              // all X/B reads done before epilogue writes
}

// ---------- main ----------
__global__ void __launch_bounds__(THREADS, 2)
ffb_main(const float* __restrict__ in_pos, const float* __restrict__ table,
         const float* __restrict__ ffn_A, const float* __restrict__ W0,
         const float* __restrict__ b0,    const float* __restrict__ bs,
         const float* __restrict__ bh,    float* __restrict__ out)
{
    extern __shared__ char sm[];
    const uint32_t sb = smem_u32(sm);
    const int t = threadIdx.x, w = t >> 5, lane = t & 31;
    const int wm = w & 1, wn = w >> 1;             // 2m x 4n warp grid
    const int base = blockIdx.x * MTILE;

    float* shpos = (float*)(sm + POS_OFF);
    float* shb   = (float*)(sm + SHB_OFF);

    if (t < 3 * MTILE) shpos[t] = in_pos[base * 3 + t];
    __syncthreads();

    // ---- hash-grid encode: 512 tasks = 64 pts x 8 corners (bit-exact, validated) ----
    // results stored as fp16 ldmatrix tiles: shgh[l][m] = 8 halves (16B)
#pragma unroll
    for (int rep = 0; rep < 2; rep++) {
        int task = t + THREADS * rep;
        int m = task >> 3, c = task & 7;
        const unsigned ox = (c >> 2) & 1u, oy = (c >> 1) & 1u, oz = c & 1u;
        const float px = (shpos[3*m + 0] + 1.0f) * 0.5f;
        const float py = (shpos[3*m + 1] + 1.0f) * 0.5f;
        const float pz = (shpos[3*m + 2] + 1.0f) * 0.5f;
#pragma unroll
        for (int l = 0; l < 4; l++) {
            const float res = (float)(16 << l);
            float sx = px*res, sy = py*res, sz = pz*res;
            float fx = floorf(sx), fy = floorf(sy), fz = floorf(sz);
            float rx = sx-fx, ry = sy-fy, rz = sz-fz;
            unsigned ux = (unsigned)fx + ox, uy = (unsigned)fy + oy, uz = (unsigned)fz + oz;
            unsigned idx = (ux ^ (uy * 2654435761u) ^ (uz * 805459861u)) & 32767u;
            const float4* fp = (const float4*)(table + ((size_t)(l << 15) + idx) * 8);
            float4 f0 = __ldg(fp), f1 = __ldg(fp + 1);
            float wt = (ox ? rx : 1.0f-rx) * (oy ? ry : 1.0f-ry) * (oz ? rz : 1.0f-rz);
            float v[8] = { f0.x*wt, f0.y*wt, f0.z*wt, f0.w*wt,
                           f1.x*wt, f1.y*wt, f1.z*wt, f1.w*wt };
#pragma unroll
            for (int s = 1; s < 8; s <<= 1)
#pragma unroll
                for (int j = 0; j < 8; j++)
                    v[j] += __shfl_xor_sync(0xffffffffu, v[j], s);
            if (c == 0) {
                __half2 h0 = __floats2half2_rn(v[0], v[1]);
                __half2 h1 = __floats2half2_rn(v[2], v[3]);
                __half2 h2 = __floats2half2_rn(v[4], v[5]);
                __half2 h3 = __floats2half2_rn(v[6], v[7]);
                uint4 pk = make_uint4(*(uint32_t*)&h0, *(uint32_t*)&h1,
                                      *(uint32_t*)&h2, *(uint32_t*)&h3);
                *(uint4*)(sm + SHGH_OFF + (uint32_t)(((l << 6) + m) << 4)) = pk;
            }
        }
    }

    // ---- layer 0: X = sin(pos @ W0 + b0) -> fp16 smem ----
    {
        const int k = t;
        const float wx = __ldg(W0 + k), wy = __ldg(W0 + 256 + k),
                    wz = __ldg(W0 + 512 + k), bb = __ldg(b0 + k);
#pragma unroll 8
        for (int m = 0; m < MTILE; m++) {
            float a = fmaf(shpos[3*m], wx, fmaf(shpos[3*m+1], wy, fmaf(shpos[3*m+2], wz, bb)));
            store_x(sm, m, k, __sinf(a));
        }
    }

    float acc[2][8][4];

#pragma unroll 1
    for (int l = 0; l < 4; l++) {
        __syncthreads();   // guard shb/shAh overwrite vs prev layer's reads
        const float gsc = 6.2831853071795864f * (float)(1 << l);
        // A' fp16 tile: shAh[n][8f], one 16B row per n (t = n)
        {
            const float* Ap = ffn_A + (l << 11) + t;   // idx (l*8+f)*256 + n
            __half2 h0 = __floats2half2_rn(__ldg(Ap)        * gsc, __ldg(Ap + 256)  * gsc);
            __half2 h1 = __floats2half2_rn(__ldg(Ap + 512)  * gsc, __ldg(Ap + 768)  * gsc);
            __half2 h2 = __floats2half2_rn(__ldg(Ap + 1024) * gsc, __ldg(Ap + 1280) * gsc);
            __half2 h3 = __floats2half2_rn(__ldg(Ap + 1536) * gsc, __ldg(Ap + 1792) * gsc);
            uint4 pk = make_uint4(*(uint32_t*)&h0, *(uint32_t*)&h1,
                                  *(uint32_t*)&h2, *(uint32_t*)&h3);
            *(uint4*)(sm + SHAH_OFF + ((uint32_t)t << 4)) = pk;
        }
        shb[t]       = __ldg(bs + (l << 8) + t);
        shb[256 + t] = __ldg(bh + (l << 8) + t);
        __syncthreads();   // shAh/shb visible before g-MMA / epilogues

        // ---- grid branch via tensor core: G = grid @ A'; sing = sin(G) packed fp16 ----
        uint32_t sing[2][8][2];
        {
            float G[2][8][4];
#pragma unroll
            for (int mt = 0; mt < 2; mt++)
#pragma unroll
                for (int nt = 0; nt < 8; nt++)
#pragma unroll
                    for (int r = 0; r < 4; r++) G[mt][nt][r] = 0.0f;
            uint32_t ga[2][2], gb[8];
#pragma unroll
            for (int mt = 0; mt < 2; mt++) {
                int row = wm * 32 + mt * 16 + (lane & 15);
                ldsm2(ga[mt], sb + SHGH_OFF + (uint32_t)(((l << 6) + row) << 4));
            }
#pragma unroll
            for (int hq = 0; hq < 2; hq++) {
                int nrow = wn * 64 + hq * 32 + (lane & 31);
                ldsm4(gb + hq * 4, sb + SHAH_OFF + ((uint32_t)nrow << 4));
            }
#pragma unroll
            for (int mt = 0; mt < 2; mt++)
#pragma unroll
                for (int nt = 0; nt < 8; nt++)
                    mma16808(G[mt][nt], ga[mt], gb[nt]);
#pragma unroll
            for (int mt = 0; mt < 2; mt++)
#pragma unroll
                for (int nt = 0; nt < 8; nt++)
#pragma unroll
                    for (int h = 0; h < 2; h++) {
                        __half2 hv = __floats2half2_rn(__sinf(G[mt][nt][h*2]),
                                                       __sinf(G[mt][nt][h*2+1]));
                        sing[mt][nt][h] = *(uint32_t*)&hv;
                    }
        }

        // GEMM1: S = X @ Ws[l]
        run_gemm(sb, l * 2, t, lane, wm, wn, acc);

        // epilogue1: x = sin(S+bs) + sing; write new X (half2 stores)
#pragma unroll
        for (int nt = 0; nt < 8; nt++) {
            const int n0 = wn * 64 + nt * 8 + (lane & 3) * 2;
            const float b0v = shb[n0], b1v = shb[n0 + 1];
#pragma unroll
            for (int mh = 0; mh < 4; mh++) {
                const int mt = mh >> 1, h = mh & 1;
                const int m = wm * 32 + mt * 16 + (lane >> 2) + h * 8;
                float2 gg = __half22float2(*(__half2*)&sing[mt][nt][h]);
                float x0 = __sinf(acc[mt][nt][h * 2 + 0] + b0v) + gg.x;
                float x1 = __sinf(acc[mt][nt][h * 2 + 1] + b1v) + gg.y;
                uint32_t c = (uint32_t)(n0 >> 3);
                uint32_t o = ((uint32_t)m << 9) + ((c ^ (uint32_t)(m & 7)) << 4)
                           + (((uint32_t)n0 & 7u) << 1);
                *(__half2*)(sm + X_OFF + o) =
                    __halves2half2(__float2half_rn(x0), __float2half_rn(x1));
            }
        }
        // GEMM2 reads of X ordered after these writes by its first __syncthreads

        // GEMM2: D = X @ Wh[l]
        run_gemm(sb, l * 2 + 1, t, lane, wm, wn, acc);

        // epilogue2: out[m][n] (+)= sin(D + bh)   (exclusive cell ownership)
#pragma unroll
        for (int nt = 0; nt < 8; nt++) {
            const int n = wn * 64 + nt * 8 + (lane & 3) * 2;
            const float b0v = shb[256 + n], b1v = shb[256 + n + 1];
#pragma unroll
            for (int mh = 0; mh < 4; mh++) {
                const int mt = mh >> 1, h = mh & 1;
                const int m = wm * 32 + mt * 16 + (lane >> 2) + h * 8;
                float v0 = __sinf(acc[mt][nt][h * 2 + 0] + b0v);
                float v1 = __sinf(acc[mt][nt][h * 2 + 1] + b1v);
                float2* p = (float2*)(out + (size_t)(base + m) * 256 + n);
                if (l == 0) {
                    *p = make_float2(v0, v1);
                } else {
                    float2 o = *p;
                    *p = make_float2(o.x + v0, o.y + v1);
                }
            }
        }
    }
}

extern "C" void kernel_launch(void* const* d_in, const int* in_sizes, int n_in,
                              void* d_out, int out_size)
{
    const float* in_pos = (const float*)d_in[0];
    const float* table  = (const float*)d_in[1];
    const float* ffn_A  = (const float*)d_in[2];
    const float* W0     = (const float*)d_in[3];
    const float* b0     = (const float*)d_in[4];
    const float* Ws     = (const float*)d_in[5];
    const float* bs     = (const float*)d_in[6];
    const float* Wh     = (const float*)d_in[7];
    const float* bh     = (const float*)d_in[8];
    float* out = (float*)d_out;

    cudaFuncSetAttribute(ffb_main, cudaFuncAttributeMaxDynamicSharedMemorySize, SMEM_BYTES);

    prep_kernel<<<(8 * 65536 + 255) / 256, 256>>>(Ws, Wh);
    ffb_main<<<NBLK, THREADS, SMEM_BYTES>>>(in_pos, table, ffn_A, W0, b0, bs, bh, out);
}